// round 6
// baseline (speedup 1.0000x reference)
#include <cuda_runtime.h>
#include <cuda_bf16.h>
#include <cstdint>

#define BQ   1024
#define SEQ  96
#define IN   128
#define HH   1024
#define G4   4096
#define KT   1152   // IN + HH
#define HOR  24
#define OUTD 128

#define NKT     (KT / 32)        // 36 k-tiles
#define STAGE_F (128 * 36 + 256 * 36)   // floats per pipeline stage (13824)
#define NSTAGE  3

// ---------------- device scratch (static, no allocs) ----------------
__device__ float g_xT[SEQ * BQ * IN];    // time-major x, tf32-rounded
__device__ float g_We[G4 * KT];          // gate-interleaved [j*4+g][k], tf32
__device__ float g_Wd[G4 * KT];          // gate-interleaved, tf32
__device__ float g_Wfc[HH * HH];
__device__ float g_Wfcc[HH * HH];
__device__ float g_Wout[OUTD * HH];
__device__ float g_be[G4];               // packed bias, n' = j*4+g order
__device__ float g_bd[G4];
__device__ float g_hA[BQ * HH];
__device__ float g_hB[BQ * HH];
__device__ float g_c[BQ * HH];
__device__ float g_hdA[BQ * HH];
__device__ float g_hdB[BQ * HH];
__device__ float g_cd[BQ * HH];
__device__ float g_out[BQ * OUTD];

__device__ __forceinline__ float to_tf32(float x) {
    uint32_t r;
    asm("cvt.rna.tf32.f32 %0, %1;" : "=r"(r) : "f"(x));
    return __uint_as_float(r);
}

__device__ __forceinline__ void mma8(float* c, const uint32_t* a, const uint32_t* b) {
    asm volatile(
        "mma.sync.aligned.m16n8k8.row.col.f32.tf32.tf32.f32 "
        "{%0,%1,%2,%3}, {%4,%5,%6,%7}, {%8,%9}, {%0,%1,%2,%3};"
        : "+f"(c[0]), "+f"(c[1]), "+f"(c[2]), "+f"(c[3])
        : "r"(a[0]), "r"(a[1]), "r"(a[2]), "r"(a[3]), "r"(b[0]), "r"(b[1]));
}

__device__ __forceinline__ void cp16(float* dst_smem, const float* src) {
    uint32_t d = (uint32_t)__cvta_generic_to_shared(dst_smem);
    asm volatile("cp.async.cg.shared.global [%0], [%1], 16;" :: "r"(d), "l"(src));
}
__device__ __forceinline__ void cp_commit() {
    asm volatile("cp.async.commit_group;");
}
template <int N> __device__ __forceinline__ void cp_wait() {
    asm volatile("cp.async.wait_group %0;" :: "n"(N));
}

// ================= fused GEMM + LSTM cell step (3-stage cp.async) =========
// Block: 128 rows x 64 j-cols (x4 gates interleaved in n'). grid = (8, 16).
__global__ void __launch_bounds__(256, 1)
lstm_step(const float* __restrict__ Ax,   // [BQ][IN]
          const float* __restrict__ Ah,   // [BQ][HH]
          const float* __restrict__ W,    // [G4][KT], n' = j*4+g row order
          const float* __restrict__ bias, // [G4] packed n' order
          float* __restrict__ c_io,       // [BQ][HH] fp32, in-place
          float* __restrict__ h_out)      // [BQ][HH] tf32-rounded fp32
{
    extern __shared__ float sm[];
    float* sbias = sm + NSTAGE * STAGE_F;   // [256]

    const int m0 = blockIdx.x * 128;
    const int n0 = blockIdx.y * 64;          // j-col base
    const int n4 = n0 * 4;                   // n' row base into W
    const int tid = threadIdx.x;
    const int warp = tid >> 5, lane = tid & 31;
    const int wm = warp >> 2, wn = warp & 3;
    const int grp = lane >> 2, tig = lane & 3;

    // stage packed bias for this block's 64 j-cols (256 n' values)
    sbias[tid] = bias[n4 + tid];

    float acc[4][8][4];
#pragma unroll
    for (int i = 0; i < 4; i++)
#pragma unroll
        for (int j = 0; j < 8; j++)
#pragma unroll
            for (int k = 0; k < 4; k++) acc[i][j][k] = 0.f;

    // ---- async tile loader ----
    auto load_tile = [&](int stage, int kt) {
        float* As = sm + stage * STAGE_F;
        float* Bs = As + 128 * 36;
        const int k0 = kt * 32;
#pragma unroll
        for (int it = 0; it < 4; it++) {
            int idx = tid + it * 256;
            int r = idx >> 3, v = idx & 7;
            const float* src = (k0 < IN)
                ? (Ax + (size_t)(m0 + r) * IN + k0 + v * 4)
                : (Ah + (size_t)(m0 + r) * HH + (k0 - IN) + v * 4);
            cp16(As + r * 36 + v * 4, src);
        }
#pragma unroll
        for (int it = 0; it < 8; it++) {
            int idx = tid + it * 256;
            int r = idx >> 3, v = idx & 7;
            cp16(Bs + r * 36 + v * 4, W + (size_t)(n4 + r) * KT + k0 + v * 4);
        }
        cp_commit();
    };

    // prologue: stages 0,1
    load_tile(0, 0);
    load_tile(1, 1);

    for (int kt = 0; kt < NKT; kt++) {
        cp_wait<1>();
        __syncthreads();
        if (kt + 2 < NKT) load_tile((kt + 2) % NSTAGE, kt + 2);

        const float* As = sm + (kt % NSTAGE) * STAGE_F;
        const float* Bs = As + 128 * 36;
#pragma unroll
        for (int ks = 0; ks < 4; ks++) {
            uint32_t af[4][4], bf[8][2];
#pragma unroll
            for (int ms = 0; ms < 4; ms++) {
                int r = wm * 64 + ms * 16 + grp;
                af[ms][0] = __float_as_uint(As[r * 36 + ks * 8 + tig]);
                af[ms][1] = __float_as_uint(As[(r + 8) * 36 + ks * 8 + tig]);
                af[ms][2] = __float_as_uint(As[r * 36 + ks * 8 + tig + 4]);
                af[ms][3] = __float_as_uint(As[(r + 8) * 36 + ks * 8 + tig + 4]);
            }
#pragma unroll
            for (int ns = 0; ns < 8; ns++) {
                int nb = wn * 64 + ns * 8 + grp;
                bf[ns][0] = __float_as_uint(Bs[nb * 36 + ks * 8 + tig]);
                bf[ns][1] = __float_as_uint(Bs[nb * 36 + ks * 8 + tig + 4]);
            }
#pragma unroll
            for (int ms = 0; ms < 4; ms++)
#pragma unroll
                for (int ns = 0; ns < 8; ns++)
                    mma8(acc[ms][ns], af[ms], bf[ns]);
        }
        __syncthreads();
    }

    // -------- epilogue: lane-pair shuffle gathers the 4 gates --------
    // n' = j*4+g: tig even lanes hold (i,f), odd lanes hold (g,o) of same j.
    const int p = tig & 1;
#pragma unroll
    for (int ms = 0; ms < 4; ms++) {
        const int b = m0 + wm * 64 + ms * 16 + grp + (p ? 8 : 0);
#pragma unroll
        for (int ns = 0; ns < 8; ns++) {
            float c0 = acc[ms][ns][0], c1 = acc[ms][ns][1];
            float c2 = acc[ms][ns][2], c3 = acc[ms][ns][3];
            float s0 = p ? c0 : c2;
            float s1 = p ? c1 : c3;
            float v0 = __shfl_xor_sync(0xffffffffu, s0, 1);
            float v1 = __shfl_xor_sync(0xffffffffu, s1, 1);
            float gi, gf, gg, go;
            if (p == 0) { gi = c0; gf = c1; gg = v0; go = v1; }
            else        { gi = v0; gf = v1; gg = c2; go = c3; }
            const int jl = wn * 16 + ns * 2 + (tig >> 1);
            gi += sbias[jl * 4 + 0];
            gf += sbias[jl * 4 + 1];
            gg += sbias[jl * 4 + 2];
            go += sbias[jl * 4 + 3];
            const int col = n0 + jl;
            float co = c_io[(size_t)b * HH + col];
            float si = 1.f / (1.f + __expf(-gi));
            float sf = 1.f / (1.f + __expf(-gf));
            float so = 1.f / (1.f + __expf(-go));
            float cn = sf * co + si * tanhf(gg);
            float hn = so * tanhf(cn);
            c_io[(size_t)b * HH + col] = cn;
            h_out[(size_t)b * HH + col] = to_tf32(hn);
        }
    }
}

// ================= generic linear: C = A @ W^T + bias =================
template <int BM>
__global__ void __launch_bounds__(256)
linear_k(const float* __restrict__ A, const float* __restrict__ W,
         const float* __restrict__ bias,
         float* __restrict__ outf, int ldf,
         float* __restrict__ outt, int ldt)
{
    __shared__ float As[BM * 36];
    __shared__ float Bs[128 * 36];
    const int m0 = blockIdx.x * BM;
    const int n0 = blockIdx.y * 128;
    const int tid = threadIdx.x;
    const int warp = tid >> 5, lane = tid & 31;
    const int wm = warp >> 2, wn = warp & 3;
    const int grp = lane >> 2, tig = lane & 3;
    constexpr int MS = BM / 32;

    float acc[MS][4][4];
#pragma unroll
    for (int i = 0; i < MS; i++)
#pragma unroll
        for (int j = 0; j < 4; j++)
#pragma unroll
            for (int k = 0; k < 4; k++) acc[i][j][k] = 0.f;

    for (int kt = 0; kt < HH / 32; kt++) {
        const int k0 = kt * 32;
        __syncthreads();
#pragma unroll
        for (int it = 0; it < BM / 32; it++) {
            int idx = tid + it * 256;
            int r = idx >> 3, v = idx & 7;
            *(float4*)(As + r * 36 + v * 4) =
                *(const float4*)(A + (size_t)(m0 + r) * HH + k0 + v * 4);
        }
#pragma unroll
        for (int it = 0; it < 4; it++) {
            int idx = tid + it * 256;
            int r = idx >> 3, v = idx & 7;
            *(float4*)(Bs + r * 36 + v * 4) =
                *(const float4*)(W + (size_t)(n0 + r) * HH + k0 + v * 4);
        }
        __syncthreads();
#pragma unroll
        for (int ks = 0; ks < 4; ks++) {
            uint32_t af[MS][4], bf[4][2];
#pragma unroll
            for (int ms = 0; ms < MS; ms++) {
                int r = wm * (BM / 2) + ms * 16 + grp;
                af[ms][0] = __float_as_uint(As[r * 36 + ks * 8 + tig]);
                af[ms][1] = __float_as_uint(As[(r + 8) * 36 + ks * 8 + tig]);
                af[ms][2] = __float_as_uint(As[r * 36 + ks * 8 + tig + 4]);
                af[ms][3] = __float_as_uint(As[(r + 8) * 36 + ks * 8 + tig + 4]);
            }
#pragma unroll
            for (int ns = 0; ns < 4; ns++) {
                int nb = wn * 32 + ns * 8 + grp;
                bf[ns][0] = __float_as_uint(Bs[nb * 36 + ks * 8 + tig]);
                bf[ns][1] = __float_as_uint(Bs[nb * 36 + ks * 8 + tig + 4]);
            }
#pragma unroll
            for (int ms = 0; ms < MS; ms++)
#pragma unroll
                for (int ns = 0; ns < 4; ns++)
                    mma8(acc[ms][ns], af[ms], bf[ns]);
        }
    }
#pragma unroll
    for (int ms = 0; ms < MS; ms++) {
#pragma unroll
        for (int ns = 0; ns < 4; ns++) {
            int rl = wm * (BM / 2) + ms * 16 + grp;
            int cl = wn * 32 + ns * 8 + tig * 2;
            float v0 = acc[ms][ns][0] + bias[n0 + cl];
            float v1 = acc[ms][ns][1] + bias[n0 + cl + 1];
            float v2 = acc[ms][ns][2] + bias[n0 + cl];
            float v3 = acc[ms][ns][3] + bias[n0 + cl + 1];
            int r0 = m0 + rl, r1 = m0 + rl + 8, cg = n0 + cl;
            if (outf) {
                outf[(size_t)r0 * ldf + cg]     = v0;
                outf[(size_t)r0 * ldf + cg + 1] = v1;
                outf[(size_t)r1 * ldf + cg]     = v2;
                outf[(size_t)r1 * ldf + cg + 1] = v3;
            }
            if (outt) {
                outt[(size_t)r0 * ldt + cg]     = to_tf32(v0);
                outt[(size_t)r0 * ldt + cg + 1] = to_tf32(v1);
                outt[(size_t)r1 * ldt + cg]     = to_tf32(v2);
                outt[(size_t)r1 * ldt + cg + 1] = to_tf32(v3);
            }
        }
    }
}

// ================= prep kernels =================
__global__ void k_prep_x(const float* __restrict__ x) {
    for (int idx = blockIdx.x * blockDim.x + threadIdx.x; idx < SEQ * BQ * IN;
         idx += gridDim.x * blockDim.x) {
        int i = idx % IN;
        int rem = idx / IN;
        int b = rem % BQ;
        int t = rem / BQ;
        g_xT[idx] = to_tf32(x[(size_t)(b * SEQ + t) * IN + i]);
    }
}

// pack W rows gate-interleaved: n' = j*4 + g  <-  original row g*HH + j
__global__ void k_prep_w(const float* __restrict__ wih, const float* __restrict__ whh,
                         const float* __restrict__ bih, const float* __restrict__ bhh,
                         float* __restrict__ Wo, float* __restrict__ bo) {
    for (size_t idx = blockIdx.x * blockDim.x + threadIdx.x; idx < (size_t)G4 * KT;
         idx += (size_t)gridDim.x * blockDim.x) {
        int np = (int)(idx / KT), k = (int)(idx % KT);
        int j = np >> 2, g = np & 3;
        int row = g * HH + j;
        float v = (k < IN) ? wih[(size_t)row * IN + k] : whh[(size_t)row * HH + (k - IN)];
        Wo[idx] = to_tf32(v);
        if (idx < G4) {
            int jj = (int)idx >> 2, gg = (int)idx & 3;
            bo[idx] = bih[gg * HH + jj] + bhh[gg * HH + jj];
        }
    }
}

__global__ void k_round(const float* __restrict__ s, float* __restrict__ d, int n) {
    for (int idx = blockIdx.x * blockDim.x + threadIdx.x; idx < n;
         idx += gridDim.x * blockDim.x)
        d[idx] = to_tf32(s[idx]);
}

__global__ void k_zero() {
    for (int idx = blockIdx.x * blockDim.x + threadIdx.x; idx < BQ * HH;
         idx += gridDim.x * blockDim.x) {
        g_hA[idx] = 0.f;
        g_c[idx] = 0.f;
        if (idx < BQ * OUTD) g_out[idx] = 0.f;
    }
}

// ================= launch =================
extern "C" void kernel_launch(void* const* d_in, const int* in_sizes, int n_in,
                              void* d_out, int out_size)
{
    const float* x     = (const float*)d_in[0];
    const float* Wih_e = (const float*)d_in[1];
    const float* Whh_e = (const float*)d_in[2];
    const float* bih_e = (const float*)d_in[3];
    const float* bhh_e = (const float*)d_in[4];
    const float* Wih_d = (const float*)d_in[5];
    const float* Whh_d = (const float*)d_in[6];
    const float* bih_d = (const float*)d_in[7];
    const float* bhh_d = (const float*)d_in[8];
    const float* Wfc   = (const float*)d_in[9];
    const float* bfc   = (const float*)d_in[10];
    const float* Wfcc  = (const float*)d_in[11];
    const float* bfcc  = (const float*)d_in[12];
    const float* Wout  = (const float*)d_in[13];
    const float* bout  = (const float*)d_in[14];
    float* out = (float*)d_out;

    float *p_xT, *p_We, *p_Wd, *p_Wfc, *p_Wfcc, *p_Wout, *p_be, *p_bd;
    float *p_hA, *p_hB, *p_c, *p_hdA, *p_hdB, *p_cd, *p_out;
    cudaGetSymbolAddress((void**)&p_xT, g_xT);
    cudaGetSymbolAddress((void**)&p_We, g_We);
    cudaGetSymbolAddress((void**)&p_Wd, g_Wd);
    cudaGetSymbolAddress((void**)&p_Wfc, g_Wfc);
    cudaGetSymbolAddress((void**)&p_Wfcc, g_Wfcc);
    cudaGetSymbolAddress((void**)&p_Wout, g_Wout);
    cudaGetSymbolAddress((void**)&p_be, g_be);
    cudaGetSymbolAddress((void**)&p_bd, g_bd);
    cudaGetSymbolAddress((void**)&p_hA, g_hA);
    cudaGetSymbolAddress((void**)&p_hB, g_hB);
    cudaGetSymbolAddress((void**)&p_c, g_c);
    cudaGetSymbolAddress((void**)&p_hdA, g_hdA);
    cudaGetSymbolAddress((void**)&p_hdB, g_hdB);
    cudaGetSymbolAddress((void**)&p_cd, g_cd);
    cudaGetSymbolAddress((void**)&p_out, g_out);

    const int smem = (NSTAGE * STAGE_F + 256) * (int)sizeof(float);  // 166912 B
    cudaFuncSetAttribute(lstm_step, cudaFuncAttributeMaxDynamicSharedMemorySize, smem);

    // prep (deterministic, idempotent)
    k_prep_x<<<2048, 256>>>(x);
    k_prep_w<<<2048, 256>>>(Wih_e, Whh_e, bih_e, bhh_e, p_We, p_be);
    k_prep_w<<<2048, 256>>>(Wih_d, Whh_d, bih_d, bhh_d, p_Wd, p_bd);
    k_round<<<1024, 256>>>(Wfc, p_Wfc, HH * HH);
    k_round<<<1024, 256>>>(Wfcc, p_Wfcc, HH * HH);
    k_round<<<256, 256>>>(Wout, p_Wout, OUTD * HH);
    k_zero<<<1024, 256>>>();

    // encoder: 96 steps, h ping-pong
    float* hb[2] = {p_hA, p_hB};
    dim3 gstep(8, 16);
    for (int t = 0; t < SEQ; t++)
        lstm_step<<<gstep, 256, smem>>>(p_xT + (size_t)t * BQ * IN, hb[t & 1],
                                        p_We, p_be, p_c, hb[(t + 1) & 1]);
    float* henc = hb[SEQ & 1];

    // bridge
    linear_k<128><<<dim3(8, 8), 256>>>(henc, p_Wfc, bfc, nullptr, 0, p_hdA, HH);
    linear_k<128><<<dim3(8, 8), 256>>>(henc, p_Wfcc, bfcc, p_cd, HH, nullptr, 0);

    // decoder: 24 steps (lstm + output projection)
    float* hd[2] = {p_hdA, p_hdB};
    for (int t = 0; t < HOR; t++) {
        lstm_step<<<gstep, 256, smem>>>(p_out, hd[t & 1], p_Wd, p_bd, p_cd,
                                        hd[(t + 1) & 1]);
        linear_k<64><<<dim3(16, 1), 256>>>(hd[(t + 1) & 1], p_Wout, bout,
                                           out + (size_t)t * OUTD, HOR * OUTD,
                                           p_out, OUTD);
    }
}

// round 8
// speedup vs baseline: 1.2453x; 1.2453x over previous
#include <cuda_runtime.h>
#include <cuda_bf16.h>
#include <cstdint>

#define BQ   1024
#define SEQ  96
#define IN   128
#define HH   1024
#define G4   4096
#define KT   1152   // IN + HH (encoder)
#define HOR  24
#define OUTD 128

// ---------------- device scratch (static, no allocs) ----------------
__device__ float g_xT[SEQ * BQ * IN];     // time-major x, tf32
__device__ float g_We[G4 * KT];           // [W_ih_e | W_hh_e], tf32
__device__ float g_Wd[G4 * HH];           // folded decoder W (steps >=1), tf32
__device__ float g_Wd0[G4 * HH];          // plain W_hh_d (step 0), tf32
__device__ float g_fold[G4 * HH];         // W_ih_d @ W_out (fp32)
__device__ float g_Wfc[HH * HH];
__device__ float g_Wfcc[HH * HH];
__device__ float g_WoutT[HH * OUTD];      // W_out^T, tf32 (fold GEMM operand)
__device__ float g_be[G4];
__device__ float g_bd[G4];                // folded bias (steps >=1)
__device__ float g_bd0[G4];               // plain bias (step 0)
__device__ float g_foldb[G4];             // W_ih_d @ b_out
__device__ float g_hA[BQ * HH];
__device__ float g_hB[BQ * HH];
__device__ float g_c[BQ * HH];
__device__ float g_cd[BQ * HH];
__device__ float g_hd_all[(HOR + 1) * BQ * HH];   // decoder h slices 0..24

__device__ __forceinline__ float to_tf32(float x) {
    uint32_t r;
    asm("cvt.rna.tf32.f32 %0, %1;" : "=r"(r) : "f"(x));
    return __uint_as_float(r);
}

__device__ __forceinline__ void mma8(float* c, const uint32_t* a, const uint32_t* b) {
    asm volatile(
        "mma.sync.aligned.m16n8k8.row.col.f32.tf32.tf32.f32 "
        "{%0,%1,%2,%3}, {%4,%5,%6,%7}, {%8,%9}, {%0,%1,%2,%3};"
        : "+f"(c[0]), "+f"(c[1]), "+f"(c[2]), "+f"(c[3])
        : "r"(a[0]), "r"(a[1]), "r"(a[2]), "r"(a[3]), "r"(b[0]), "r"(b[1]));
}

// ================= fused GEMM + LSTM cell step =================
// Block tile: 128 rows x (4 gates x 64 cols). grid = (8, 16).
template <int KTOT, bool HAS_X>
__global__ void __launch_bounds__(256, 1)
lstm_step(const float* __restrict__ Ax,   // [BQ][IN] (encoder only)
          const float* __restrict__ Ah,   // [BQ][HH]
          const float* __restrict__ W,    // [G4][KTOT]
          const float* __restrict__ bias, // [G4]
          float* __restrict__ c_io,       // [BQ][HH] fp32, in-place
          float* __restrict__ h_out)      // [BQ][HH] tf32-rounded fp32
{
    extern __shared__ float sm[];
    float* As = sm;              // [128][36]
    float* Bs = sm + 128 * 36;   // [256][36]

    const int m0 = blockIdx.x * 128;
    const int n0 = blockIdx.y * 64;
    const int tid = threadIdx.x;
    const int warp = tid >> 5, lane = tid & 31;
    const int wm = warp >> 2, wn = warp & 3;       // 2 x 4 warps; wn == gate
    const int grp = lane >> 2, tig = lane & 3;

    float acc[4][8][4];
#pragma unroll
    for (int i = 0; i < 4; i++)
#pragma unroll
        for (int j = 0; j < 8; j++)
#pragma unroll
            for (int k = 0; k < 4; k++) acc[i][j][k] = 0.f;

    for (int kt = 0; kt < KTOT / 32; kt++) {
        const int k0 = kt * 32;
        __syncthreads();
        // stage A tile 128x32 (float4)
#pragma unroll
        for (int it = 0; it < 4; it++) {
            int idx = tid + it * 256;
            int r = idx >> 3, v = idx & 7;
            const float* src;
            if (HAS_X)
                src = (k0 < IN)
                    ? (Ax + (size_t)(m0 + r) * IN + k0 + v * 4)
                    : (Ah + (size_t)(m0 + r) * HH + (k0 - IN) + v * 4);
            else
                src = Ah + (size_t)(m0 + r) * HH + k0 + v * 4;
            *(float4*)(As + r * 36 + v * 4) = *(const float4*)src;
        }
        // stage B tile 256x32: rows = 4 gate chunks of 64 W-rows
#pragma unroll
        for (int it = 0; it < 8; it++) {
            int idx = tid + it * 256;
            int r = idx >> 3, v = idx & 7;
            int gate = r >> 6, jj = r & 63;
            const float* src = W + (size_t)(gate * HH + n0 + jj) * KTOT + k0 + v * 4;
            *(float4*)(Bs + r * 36 + v * 4) = *(const float4*)src;
        }
        __syncthreads();
#pragma unroll
        for (int ks = 0; ks < 4; ks++) {
            uint32_t af[4][4], bf[8][2];
#pragma unroll
            for (int ms = 0; ms < 4; ms++) {
                int r = wm * 64 + ms * 16 + grp;
                af[ms][0] = __float_as_uint(As[r * 36 + ks * 8 + tig]);
                af[ms][1] = __float_as_uint(As[(r + 8) * 36 + ks * 8 + tig]);
                af[ms][2] = __float_as_uint(As[r * 36 + ks * 8 + tig + 4]);
                af[ms][3] = __float_as_uint(As[(r + 8) * 36 + ks * 8 + tig + 4]);
            }
#pragma unroll
            for (int ns = 0; ns < 8; ns++) {
                int nb = wn * 64 + ns * 8 + grp;
                bf[ns][0] = __float_as_uint(Bs[nb * 36 + ks * 8 + tig]);
                bf[ns][1] = __float_as_uint(Bs[nb * 36 + ks * 8 + tig + 4]);
            }
#pragma unroll
            for (int ms = 0; ms < 4; ms++)
#pragma unroll
                for (int ns = 0; ns < 8; ns++)
                    mma8(acc[ms][ns], af[ms], bf[ns]);
        }
    }

    // -------- epilogue: gather all 4 gates per (b,j) via smem --------
    __syncthreads();
    float* Cs = sm;  // [128][264] fp32, reuses staging
#pragma unroll
    for (int ms = 0; ms < 4; ms++) {
#pragma unroll
        for (int ns = 0; ns < 8; ns++) {
            int r = wm * 64 + ms * 16 + grp;
            int cc = wn * 64 + ns * 8 + tig * 2;
            Cs[r * 264 + cc]           = acc[ms][ns][0];
            Cs[r * 264 + cc + 1]       = acc[ms][ns][1];
            Cs[(r + 8) * 264 + cc]     = acc[ms][ns][2];
            Cs[(r + 8) * 264 + cc + 1] = acc[ms][ns][3];
        }
    }
    __syncthreads();
    for (int e = tid; e < 128 * 64; e += 256) {
        int r = e >> 6, j = e & 63;
        int col = n0 + j;
        int b = m0 + r;
        float iv = Cs[r * 264 + j]       + bias[col];
        float fv = Cs[r * 264 + 64 + j]  + bias[HH + col];
        float gv = Cs[r * 264 + 128 + j] + bias[2 * HH + col];
        float ov = Cs[r * 264 + 192 + j] + bias[3 * HH + col];
        float co = c_io[(size_t)b * HH + col];
        float si = 1.f / (1.f + __expf(-iv));
        float sf = 1.f / (1.f + __expf(-fv));
        float so = 1.f / (1.f + __expf(-ov));
        float cn = sf * co + si * tanhf(gv);
        float hn = so * tanhf(cn);
        c_io[(size_t)b * HH + col] = cn;
        h_out[(size_t)b * HH + col] = to_tf32(hn);
    }
}

// ============ generic linear: C = A @ W^T + bias, K templated ============
// A: [M][KK], W: [N][KK]. Block BM x 128, 256 threads.
// PERM: row r maps to out[b*HOR*OUTD + t*OUTD + col] with t=r/BQ, b=r%BQ.
template <int BM, int KK, bool PERM>
__global__ void __launch_bounds__(256)
linear_k(const float* __restrict__ A, const float* __restrict__ W,
         const float* __restrict__ bias,
         float* __restrict__ outf, int ldf,
         float* __restrict__ outt, int ldt)
{
    __shared__ float As[BM * 36];
    __shared__ float Bs[128 * 36];
    const int m0 = blockIdx.x * BM;
    const int n0 = blockIdx.y * 128;
    const int tid = threadIdx.x;
    const int warp = tid >> 5, lane = tid & 31;
    const int wm = warp >> 2, wn = warp & 3;
    const int grp = lane >> 2, tig = lane & 3;
    constexpr int MS = BM / 32;

    float acc[MS][4][4];
#pragma unroll
    for (int i = 0; i < MS; i++)
#pragma unroll
        for (int j = 0; j < 4; j++)
#pragma unroll
            for (int k = 0; k < 4; k++) acc[i][j][k] = 0.f;

    for (int kt = 0; kt < KK / 32; kt++) {
        const int k0 = kt * 32;
        __syncthreads();
#pragma unroll
        for (int it = 0; it < BM / 32; it++) {
            int idx = tid + it * 256;
            int r = idx >> 3, v = idx & 7;
            *(float4*)(As + r * 36 + v * 4) =
                *(const float4*)(A + (size_t)(m0 + r) * KK + k0 + v * 4);
        }
#pragma unroll
        for (int it = 0; it < 4; it++) {
            int idx = tid + it * 256;
            int r = idx >> 3, v = idx & 7;
            *(float4*)(Bs + r * 36 + v * 4) =
                *(const float4*)(W + (size_t)(n0 + r) * KK + k0 + v * 4);
        }
        __syncthreads();
#pragma unroll
        for (int ks = 0; ks < 4; ks++) {
            uint32_t af[MS][4], bf[4][2];
#pragma unroll
            for (int ms = 0; ms < MS; ms++) {
                int r = wm * (BM / 2) + ms * 16 + grp;
                af[ms][0] = __float_as_uint(As[r * 36 + ks * 8 + tig]);
                af[ms][1] = __float_as_uint(As[(r + 8) * 36 + ks * 8 + tig]);
                af[ms][2] = __float_as_uint(As[r * 36 + ks * 8 + tig + 4]);
                af[ms][3] = __float_as_uint(As[(r + 8) * 36 + ks * 8 + tig + 4]);
            }
#pragma unroll
            for (int ns = 0; ns < 4; ns++) {
                int nb = wn * 32 + ns * 8 + grp;
                bf[ns][0] = __float_as_uint(Bs[nb * 36 + ks * 8 + tig]);
                bf[ns][1] = __float_as_uint(Bs[nb * 36 + ks * 8 + tig + 4]);
            }
#pragma unroll
            for (int ms = 0; ms < MS; ms++)
#pragma unroll
                for (int ns = 0; ns < 4; ns++)
                    mma8(acc[ms][ns], af[ms], bf[ns]);
        }
    }
#pragma unroll
    for (int ms = 0; ms < MS; ms++) {
#pragma unroll
        for (int ns = 0; ns < 4; ns++) {
            int rl = wm * (BM / 2) + ms * 16 + grp;
            int cl = wn * 32 + ns * 8 + tig * 2;
            float b0 = bias ? bias[n0 + cl] : 0.f;
            float b1 = bias ? bias[n0 + cl + 1] : 0.f;
            float v0 = acc[ms][ns][0] + b0;
            float v1 = acc[ms][ns][1] + b1;
            float v2 = acc[ms][ns][2] + b0;
            float v3 = acc[ms][ns][3] + b1;
            int r0 = m0 + rl, r1 = m0 + rl + 8, cg = n0 + cl;
            if (outf) {
                size_t a0, a1;
                if (PERM) {
                    a0 = ((size_t)(r0 % BQ) * HOR + (r0 / BQ)) * OUTD + cg;
                    a1 = ((size_t)(r1 % BQ) * HOR + (r1 / BQ)) * OUTD + cg;
                } else {
                    a0 = (size_t)r0 * ldf + cg;
                    a1 = (size_t)r1 * ldf + cg;
                }
                outf[a0]     = v0;
                outf[a0 + 1] = v1;
                outf[a1]     = v2;
                outf[a1 + 1] = v3;
            }
            if (outt) {
                outt[(size_t)r0 * ldt + cg]     = to_tf32(v0);
                outt[(size_t)r0 * ldt + cg + 1] = to_tf32(v1);
                outt[(size_t)r1 * ldt + cg]     = to_tf32(v2);
                outt[(size_t)r1 * ldt + cg + 1] = to_tf32(v3);
            }
        }
    }
}

// ================= prep kernels (exactly 5 launches pre-encoder) ==========
// (1) x transpose + round
__global__ void k_prep_x(const float* __restrict__ x) {
    for (int idx = blockIdx.x * blockDim.x + threadIdx.x; idx < SEQ * BQ * IN;
         idx += gridDim.x * blockDim.x) {
        int i = idx % IN;
        int rem = idx / IN;
        int b = rem % BQ;
        int t = rem / BQ;
        g_xT[idx] = to_tf32(x[(size_t)(b * SEQ + t) * IN + i]);
    }
}

// (2) encoder weight pack [W_ih | W_hh] + bias sum
__global__ void k_prep_w(const float* __restrict__ wih, const float* __restrict__ whh,
                         const float* __restrict__ bih, const float* __restrict__ bhh,
                         float* __restrict__ Wo, float* __restrict__ bo) {
    for (int idx = blockIdx.x * blockDim.x + threadIdx.x; idx < G4 * KT;
         idx += gridDim.x * blockDim.x) {
        int n = idx / KT, k = idx % KT;
        float v = (k < IN) ? wih[(size_t)n * IN + k] : whh[(size_t)n * HH + (k - IN)];
        Wo[idx] = to_tf32(v);
        if (idx < G4) bo[idx] = bih[idx] + bhh[idx];
    }
}

// (3) misc: round Wfc/Wfcc, transpose+round Wout, foldb, zero states
#define MISC_SEG1 (HH * HH)
#define MISC_SEG2 (2 * HH * HH)
#define MISC_SEG3 (2 * HH * HH + HH * OUTD)
#define MISC_SEG4 (2 * HH * HH + HH * OUTD + G4)
#define MISC_TOT  (2 * HH * HH + HH * OUTD + G4 + BQ * HH)
__global__ void k_misc(const float* __restrict__ Wfc, const float* __restrict__ Wfcc,
                       const float* __restrict__ Wout, const float* __restrict__ wihd,
                       const float* __restrict__ bout) {
    for (int idx = blockIdx.x * blockDim.x + threadIdx.x; idx < MISC_TOT;
         idx += gridDim.x * blockDim.x) {
        if (idx < MISC_SEG1) {
            g_Wfc[idx] = to_tf32(Wfc[idx]);
        } else if (idx < MISC_SEG2) {
            int i = idx - MISC_SEG1;
            g_Wfcc[i] = to_tf32(Wfcc[i]);
        } else if (idx < MISC_SEG3) {
            int i = idx - MISC_SEG2;           // i = j*OUTD + o
            int j = i / OUTD, o = i % OUTD;
            g_WoutT[i] = to_tf32(Wout[(size_t)o * HH + j]);
        } else if (idx < MISC_SEG4) {
            int n = idx - MISC_SEG3;
            float s = 0.f;
            for (int o = 0; o < OUTD; o++)
                s += wihd[(size_t)n * OUTD + o] * bout[o];
            g_foldb[n] = s;
        } else {
            int i = idx - MISC_SEG4;
            g_hA[i] = 0.f;
            g_c[i] = 0.f;
        }
    }
}

// (5) decoder weights: folded (steps>=1) AND plain (step 0)
__global__ void k_prep_wd(const float* __restrict__ whh,
                          const float* __restrict__ bih, const float* __restrict__ bhh) {
    for (size_t idx = blockIdx.x * blockDim.x + threadIdx.x; idx < (size_t)G4 * HH;
         idx += (size_t)gridDim.x * blockDim.x) {
        float w = whh[idx];
        g_Wd[idx]  = to_tf32(w + g_fold[idx]);
        g_Wd0[idx] = to_tf32(w);
        if (idx < G4) {
            float b = bih[idx] + bhh[idx];
            g_bd[idx]  = b + g_foldb[idx];
            g_bd0[idx] = b;
        }
    }
}

// ================= launch =================
extern "C" void kernel_launch(void* const* d_in, const int* in_sizes, int n_in,
                              void* d_out, int out_size)
{
    const float* x     = (const float*)d_in[0];
    const float* Wih_e = (const float*)d_in[1];
    const float* Whh_e = (const float*)d_in[2];
    const float* bih_e = (const float*)d_in[3];
    const float* bhh_e = (const float*)d_in[4];
    const float* Wih_d = (const float*)d_in[5];
    const float* Whh_d = (const float*)d_in[6];
    const float* bih_d = (const float*)d_in[7];
    const float* bhh_d = (const float*)d_in[8];
    const float* Wfc   = (const float*)d_in[9];
    const float* bfc   = (const float*)d_in[10];
    const float* Wfcc  = (const float*)d_in[11];
    const float* bfcc  = (const float*)d_in[12];
    const float* Wout  = (const float*)d_in[13];
    const float* bout  = (const float*)d_in[14];
    float* out = (float*)d_out;

    float *p_xT, *p_We, *p_Wd, *p_Wd0, *p_fold, *p_Wfc, *p_Wfcc, *p_WoutT;
    float *p_be, *p_bd, *p_bd0;
    float *p_hA, *p_hB, *p_c, *p_cd, *p_hd;
    cudaGetSymbolAddress((void**)&p_xT, g_xT);
    cudaGetSymbolAddress((void**)&p_We, g_We);
    cudaGetSymbolAddress((void**)&p_Wd, g_Wd);
    cudaGetSymbolAddress((void**)&p_Wd0, g_Wd0);
    cudaGetSymbolAddress((void**)&p_fold, g_fold);
    cudaGetSymbolAddress((void**)&p_Wfc, g_Wfc);
    cudaGetSymbolAddress((void**)&p_Wfcc, g_Wfcc);
    cudaGetSymbolAddress((void**)&p_WoutT, g_WoutT);
    cudaGetSymbolAddress((void**)&p_be, g_be);
    cudaGetSymbolAddress((void**)&p_bd, g_bd);
    cudaGetSymbolAddress((void**)&p_bd0, g_bd0);
    cudaGetSymbolAddress((void**)&p_hA, g_hA);
    cudaGetSymbolAddress((void**)&p_hB, g_hB);
    cudaGetSymbolAddress((void**)&p_c, g_c);
    cudaGetSymbolAddress((void**)&p_cd, g_cd);
    cudaGetSymbolAddress((void**)&p_hd, g_hd_all);

    const int smem = 128 * 264 * (int)sizeof(float);  // 135168 B
    cudaFuncSetAttribute((const void*)lstm_step<KT, true>,
                         cudaFuncAttributeMaxDynamicSharedMemorySize, smem);
    cudaFuncSetAttribute((const void*)lstm_step<HH, false>,
                         cudaFuncAttributeMaxDynamicSharedMemorySize, smem);

    // ---- prep: exactly 5 launches (ncu -s 5 profiles first lstm_step) ----
    k_prep_x<<<2048, 256>>>(x);                                          // 1
    k_prep_w<<<2048, 256>>>(Wih_e, Whh_e, bih_e, bhh_e, p_We, p_be);     // 2
    k_misc<<<2048, 256>>>(Wfc, Wfcc, Wout, Wih_d, bout);                 // 3
    // fold GEMM: g_fold[4096][1024] = W_ih_d[4096][128] @ W_out
    linear_k<128, 128, false><<<dim3(32, 8), 256>>>(Wih_d, p_WoutT, nullptr,
                                                    p_fold, HH, nullptr, 0); // 4
    k_prep_wd<<<2048, 256>>>(Whh_d, bih_d, bhh_d);                       // 5

    // ---- encoder: 96 steps, h ping-pong ----
    float* hb[2] = {p_hA, p_hB};
    dim3 gstep(8, 16);
    for (int t = 0; t < SEQ; t++)
        lstm_step<KT, true><<<gstep, 256, smem>>>(
            p_xT + (size_t)t * BQ * IN, hb[t & 1], p_We, p_be, p_c, hb[(t + 1) & 1]);
    float* henc = hb[SEQ & 1];

    // ---- bridge: h_dec -> slice 0 of g_hd_all (tf32), c_dec -> g_cd ----
    linear_k<128, HH, false><<<dim3(8, 8), 256>>>(henc, p_Wfc, bfc,
                                                  nullptr, 0, p_hd, HH);
    linear_k<128, HH, false><<<dim3(8, 8), 256>>>(henc, p_Wfcc, bfcc,
                                                  p_cd, HH, nullptr, 0);

    // ---- decoder: step 0 plain W_hh (in0 = 0!), steps 1..23 folded ----
    for (int t = 0; t < HOR; t++)
        lstm_step<HH, false><<<gstep, 256, smem>>>(
            nullptr, p_hd + (size_t)t * BQ * HH,
            (t == 0) ? p_Wd0 : p_Wd, (t == 0) ? p_bd0 : p_bd, p_cd,
            p_hd + (size_t)(t + 1) * BQ * HH);

    // ---- all 24 output projections in ONE batched GEMM ----
    linear_k<128, HH, true><<<dim3(HOR * BQ / 128, 1), 256>>>(
        p_hd + (size_t)BQ * HH, Wout, bout, out, 0, nullptr, 0);
}

// round 11
// speedup vs baseline: 1.3662x; 1.0971x over previous
#include <cuda_runtime.h>
#include <cuda_bf16.h>
#include <cstdint>

#define BQ   1024
#define SEQ  96
#define IN   128
#define HH   1024
#define G4   4096
#define KT   1152   // IN + HH (encoder)
#define HOR  24
#define OUTD 128

#define STAGE_F (128 * 36 + 256 * 36)   // 13824 floats per pipeline stage

// ---------------- device scratch (static, no allocs) ----------------
__device__ float g_xT[SEQ * BQ * IN];     // time-major x, tf32
__device__ float g_We[G4 * KT];           // [W_ih_e | W_hh_e], tf32
__device__ float g_Wd[G4 * HH];           // folded decoder W (steps >=1), tf32
__device__ float g_Wd0[G4 * HH];          // plain W_hh_d (step 0), tf32
__device__ float g_fold[G4 * HH];         // W_ih_d @ W_out (fp32)
__device__ float g_Wfc[HH * HH];
__device__ float g_Wfcc[HH * HH];
__device__ float g_WoutT[HH * OUTD];      // W_out^T, tf32
__device__ float g_be[G4];
__device__ float g_bd[G4];
__device__ float g_bd0[G4];
__device__ float g_foldb[G4];
__device__ float g_hA[BQ * HH];
__device__ float g_hB[BQ * HH];
__device__ float g_c[BQ * HH];
__device__ float g_cd[BQ * HH];
__device__ float g_hd_all[(HOR + 1) * BQ * HH];

__device__ __forceinline__ float to_tf32(float x) {
    uint32_t r;
    asm("cvt.rna.tf32.f32 %0, %1;" : "=r"(r) : "f"(x));
    return __uint_as_float(r);
}

__device__ __forceinline__ void mma8(float* c, const uint32_t* a, const uint32_t* b) {
    asm volatile(
        "mma.sync.aligned.m16n8k8.row.col.f32.tf32.tf32.f32 "
        "{%0,%1,%2,%3}, {%4,%5,%6,%7}, {%8,%9}, {%0,%1,%2,%3};"
        : "+f"(c[0]), "+f"(c[1]), "+f"(c[2]), "+f"(c[3])
        : "r"(a[0]), "r"(a[1]), "r"(a[2]), "r"(a[3]), "r"(b[0]), "r"(b[1]));
}

__device__ __forceinline__ void cp16(float* dst_smem, const float* src) {
    uint32_t d = (uint32_t)__cvta_generic_to_shared(dst_smem);
    asm volatile("cp.async.cg.shared.global [%0], [%1], 16;" :: "r"(d), "l"(src));
}
__device__ __forceinline__ void cp_commit() { asm volatile("cp.async.commit_group;"); }
template <int N> __device__ __forceinline__ void cp_wait() {
    asm volatile("cp.async.wait_group %0;" :: "n"(N));
}

// ================= fused GEMM + LSTM cell step (2-stage cp.async) =========
// Block tile: 128 rows x (4 gates x 64 cols). grid = (8, 16).
template <int KTOT, bool HAS_X>
__global__ void __launch_bounds__(256, 1)
lstm_step(const float* __restrict__ Ax,   // [BQ][IN] (encoder only)
          const float* __restrict__ Ah,   // [BQ][HH]
          const float* __restrict__ W,    // [G4][KTOT]
          const float* __restrict__ bias, // [G4]
          float* __restrict__ c_io,       // [BQ][HH] fp32, in-place
          float* __restrict__ h_out)      // [BQ][HH] tf32-rounded fp32
{
    extern __shared__ float sm[];
    constexpr int NKT = KTOT / 32;

    const int m0 = blockIdx.x * 128;
    const int n0 = blockIdx.y * 64;
    const int tid = threadIdx.x;
    const int warp = tid >> 5, lane = tid & 31;
    const int wm = warp >> 2, wn = warp & 3;       // 2 x 4 warps; wn == gate
    const int grp = lane >> 2, tig = lane & 3;

    float acc[4][8][4];
#pragma unroll
    for (int i = 0; i < 4; i++)
#pragma unroll
        for (int j = 0; j < 8; j++)
#pragma unroll
            for (int k = 0; k < 4; k++) acc[i][j][k] = 0.f;

    // ---- async tile loader into stage s ----
    auto load_tile = [&](int s, int kt) {
        float* As = sm + s * STAGE_F;
        float* Bs = As + 128 * 36;
        const int k0 = kt * 32;
#pragma unroll
        for (int it = 0; it < 4; it++) {
            int idx = tid + it * 256;
            int r = idx >> 3, v = idx & 7;
            const float* src;
            if (HAS_X)
                src = (k0 < IN)
                    ? (Ax + (size_t)(m0 + r) * IN + k0 + v * 4)
                    : (Ah + (size_t)(m0 + r) * HH + (k0 - IN) + v * 4);
            else
                src = Ah + (size_t)(m0 + r) * HH + k0 + v * 4;
            cp16(As + r * 36 + v * 4, src);
        }
#pragma unroll
        for (int it = 0; it < 8; it++) {
            int idx = tid + it * 256;
            int r = idx >> 3, v = idx & 7;
            int gate = r >> 6, jj = r & 63;
            cp16(Bs + r * 36 + v * 4,
                 W + (size_t)(gate * HH + n0 + jj) * KTOT + k0 + v * 4);
        }
        cp_commit();
    };

    load_tile(0, 0);

    for (int kt = 0; kt < NKT; kt++) {
        // issue next tile into the other stage (its previous use finished
        // before the end-of-iteration syncthreads of iter kt-1)
        if (kt + 1 < NKT) {
            load_tile((kt + 1) & 1, kt + 1);
            cp_wait<1>();       // oldest group (tile kt) complete
        } else {
            cp_wait<0>();
        }
        __syncthreads();

        const float* As = sm + (kt & 1) * STAGE_F;
        const float* Bs = As + 128 * 36;
#pragma unroll
        for (int ks = 0; ks < 4; ks++) {
            uint32_t af[4][4], bf[8][2];
#pragma unroll
            for (int ms = 0; ms < 4; ms++) {
                int r = wm * 64 + ms * 16 + grp;
                af[ms][0] = __float_as_uint(As[r * 36 + ks * 8 + tig]);
                af[ms][1] = __float_as_uint(As[(r + 8) * 36 + ks * 8 + tig]);
                af[ms][2] = __float_as_uint(As[r * 36 + ks * 8 + tig + 4]);
                af[ms][3] = __float_as_uint(As[(r + 8) * 36 + ks * 8 + tig + 4]);
            }
#pragma unroll
            for (int ns = 0; ns < 8; ns++) {
                int nb = wn * 64 + ns * 8 + grp;
                bf[ns][0] = __float_as_uint(Bs[nb * 36 + ks * 8 + tig]);
                bf[ns][1] = __float_as_uint(Bs[nb * 36 + ks * 8 + tig + 4]);
            }
#pragma unroll
            for (int ms = 0; ms < 4; ms++)
#pragma unroll
                for (int ns = 0; ns < 8; ns++)
                    mma8(acc[ms][ns], af[ms], bf[ns]);
        }
        __syncthreads();
    }

    // -------- epilogue: gather all 4 gates per (b,j) via smem --------
    float* Cs = sm;  // [128][264] fp32, reuses staging (all loads drained)
#pragma unroll
    for (int ms = 0; ms < 4; ms++) {
#pragma unroll
        for (int ns = 0; ns < 8; ns++) {
            int r = wm * 64 + ms * 16 + grp;
            int cc = wn * 64 + ns * 8 + tig * 2;
            Cs[r * 264 + cc]           = acc[ms][ns][0];
            Cs[r * 264 + cc + 1]       = acc[ms][ns][1];
            Cs[(r + 8) * 264 + cc]     = acc[ms][ns][2];
            Cs[(r + 8) * 264 + cc + 1] = acc[ms][ns][3];
        }
    }
    __syncthreads();
    for (int e = tid; e < 128 * 64; e += 256) {
        int r = e >> 6, j = e & 63;
        int col = n0 + j;
        int b = m0 + r;
        float iv = Cs[r * 264 + j]       + bias[col];
        float fv = Cs[r * 264 + 64 + j]  + bias[HH + col];
        float gv = Cs[r * 264 + 128 + j] + bias[2 * HH + col];
        float ov = Cs[r * 264 + 192 + j] + bias[3 * HH + col];
        float co = c_io[(size_t)b * HH + col];
        float si = 1.f / (1.f + __expf(-iv));
        float sf = 1.f / (1.f + __expf(-fv));
        float so = 1.f / (1.f + __expf(-ov));
        float cn = sf * co + si * tanhf(gv);
        float hn = so * tanhf(cn);
        c_io[(size_t)b * HH + col] = cn;
        h_out[(size_t)b * HH + col] = to_tf32(hn);
    }
}

// ============ generic linear: C = A @ W^T + bias, K templated ============
// PERM: row r maps to out[b*HOR*OUTD + t*OUTD + col] with t=r/BQ, b=r%BQ.
template <int BM, int KK, bool PERM>
__global__ void __launch_bounds__(256)
linear_k(const float* __restrict__ A, const float* __restrict__ W,
         const float* __restrict__ bias,
         float* __restrict__ outf, int ldf,
         float* __restrict__ outt, int ldt)
{
    __shared__ float As[BM * 36];
    __shared__ float Bs[128 * 36];
    const int m0 = blockIdx.x * BM;
    const int n0 = blockIdx.y * 128;
    const int tid = threadIdx.x;
    const int warp = tid >> 5, lane = tid & 31;
    const int wm = warp >> 2, wn = warp & 3;
    const int grp = lane >> 2, tig = lane & 3;
    constexpr int MS = BM / 32;

    float acc[MS][4][4];
#pragma unroll
    for (int i = 0; i < MS; i++)
#pragma unroll
        for (int j = 0; j < 4; j++)
#pragma unroll
            for (int k = 0; k < 4; k++) acc[i][j][k] = 0.f;

    for (int kt = 0; kt < KK / 32; kt++) {
        const int k0 = kt * 32;
        __syncthreads();
#pragma unroll
        for (int it = 0; it < BM / 32; it++) {
            int idx = tid + it * 256;
            int r = idx >> 3, v = idx & 7;
            *(float4*)(As + r * 36 + v * 4) =
                *(const float4*)(A + (size_t)(m0 + r) * KK + k0 + v * 4);
        }
#pragma unroll
        for (int it = 0; it < 4; it++) {
            int idx = tid + it * 256;
            int r = idx >> 3, v = idx & 7;
            *(float4*)(Bs + r * 36 + v * 4) =
                *(const float4*)(W + (size_t)(n0 + r) * KK + k0 + v * 4);
        }
        __syncthreads();
#pragma unroll
        for (int ks = 0; ks < 4; ks++) {
            uint32_t af[MS][4], bf[4][2];
#pragma unroll
            for (int ms = 0; ms < MS; ms++) {
                int r = wm * (BM / 2) + ms * 16 + grp;
                af[ms][0] = __float_as_uint(As[r * 36 + ks * 8 + tig]);
                af[ms][1] = __float_as_uint(As[(r + 8) * 36 + ks * 8 + tig]);
                af[ms][2] = __float_as_uint(As[r * 36 + ks * 8 + tig + 4]);
                af[ms][3] = __float_as_uint(As[(r + 8) * 36 + ks * 8 + tig + 4]);
            }
#pragma unroll
            for (int ns = 0; ns < 4; ns++) {
                int nb = wn * 32 + ns * 8 + grp;
                bf[ns][0] = __float_as_uint(Bs[nb * 36 + ks * 8 + tig]);
                bf[ns][1] = __float_as_uint(Bs[nb * 36 + ks * 8 + tig + 4]);
            }
#pragma unroll
            for (int ms = 0; ms < MS; ms++)
#pragma unroll
                for (int ns = 0; ns < 4; ns++)
                    mma8(acc[ms][ns], af[ms], bf[ns]);
        }
    }
#pragma unroll
    for (int ms = 0; ms < MS; ms++) {
#pragma unroll
        for (int ns = 0; ns < 4; ns++) {
            int rl = wm * (BM / 2) + ms * 16 + grp;
            int cl = wn * 32 + ns * 8 + tig * 2;
            float b0 = bias ? bias[n0 + cl] : 0.f;
            float b1 = bias ? bias[n0 + cl + 1] : 0.f;
            float v0 = acc[ms][ns][0] + b0;
            float v1 = acc[ms][ns][1] + b1;
            float v2 = acc[ms][ns][2] + b0;
            float v3 = acc[ms][ns][3] + b1;
            int r0 = m0 + rl, r1 = m0 + rl + 8, cg = n0 + cl;
            if (outf) {
                size_t a0, a1;
                if (PERM) {
                    a0 = ((size_t)(r0 % BQ) * HOR + (r0 / BQ)) * OUTD + cg;
                    a1 = ((size_t)(r1 % BQ) * HOR + (r1 / BQ)) * OUTD + cg;
                } else {
                    a0 = (size_t)r0 * ldf + cg;
                    a1 = (size_t)r1 * ldf + cg;
                }
                outf[a0]     = v0;
                outf[a0 + 1] = v1;
                outf[a1]     = v2;
                outf[a1 + 1] = v3;
            }
            if (outt) {
                outt[(size_t)r0 * ldt + cg]     = to_tf32(v0);
                outt[(size_t)r0 * ldt + cg + 1] = to_tf32(v1);
                outt[(size_t)r1 * ldt + cg]     = to_tf32(v2);
                outt[(size_t)r1 * ldt + cg + 1] = to_tf32(v3);
            }
        }
    }
}

// ================= prep kernels (exactly 5 launches pre-encoder) ==========
__global__ void k_prep_x(const float* __restrict__ x) {
    for (int idx = blockIdx.x * blockDim.x + threadIdx.x; idx < SEQ * BQ * IN;
         idx += gridDim.x * blockDim.x) {
        int i = idx % IN;
        int rem = idx / IN;
        int b = rem % BQ;
        int t = rem / BQ;
        g_xT[idx] = to_tf32(x[(size_t)(b * SEQ + t) * IN + i]);
    }
}

__global__ void k_prep_w(const float* __restrict__ wih, const float* __restrict__ whh,
                         const float* __restrict__ bih, const float* __restrict__ bhh,
                         float* __restrict__ Wo, float* __restrict__ bo) {
    for (int idx = blockIdx.x * blockDim.x + threadIdx.x; idx < G4 * KT;
         idx += gridDim.x * blockDim.x) {
        int n = idx / KT, k = idx % KT;
        float v = (k < IN) ? wih[(size_t)n * IN + k] : whh[(size_t)n * HH + (k - IN)];
        Wo[idx] = to_tf32(v);
        if (idx < G4) bo[idx] = bih[idx] + bhh[idx];
    }
}

#define MISC_SEG1 (HH * HH)
#define MISC_SEG2 (2 * HH * HH)
#define MISC_SEG3 (2 * HH * HH + HH * OUTD)
#define MISC_SEG4 (2 * HH * HH + HH * OUTD + G4)
#define MISC_TOT  (2 * HH * HH + HH * OUTD + G4 + BQ * HH)
__global__ void k_misc(const float* __restrict__ Wfc, const float* __restrict__ Wfcc,
                       const float* __restrict__ Wout, const float* __restrict__ wihd,
                       const float* __restrict__ bout) {
    for (int idx = blockIdx.x * blockDim.x + threadIdx.x; idx < MISC_TOT;
         idx += gridDim.x * blockDim.x) {
        if (idx < MISC_SEG1) {
            g_Wfc[idx] = to_tf32(Wfc[idx]);
        } else if (idx < MISC_SEG2) {
            int i = idx - MISC_SEG1;
            g_Wfcc[i] = to_tf32(Wfcc[i]);
        } else if (idx < MISC_SEG3) {
            int i = idx - MISC_SEG2;
            int j = i / OUTD, o = i % OUTD;
            g_WoutT[i] = to_tf32(Wout[(size_t)o * HH + j]);
        } else if (idx < MISC_SEG4) {
            int n = idx - MISC_SEG3;
            float s = 0.f;
            for (int o = 0; o < OUTD; o++)
                s += wihd[(size_t)n * OUTD + o] * bout[o];
            g_foldb[n] = s;
        } else {
            int i = idx - MISC_SEG4;
            g_hA[i] = 0.f;
            g_c[i] = 0.f;
        }
    }
}

__global__ void k_prep_wd(const float* __restrict__ whh,
                          const float* __restrict__ bih, const float* __restrict__ bhh) {
    for (size_t idx = blockIdx.x * blockDim.x + threadIdx.x; idx < (size_t)G4 * HH;
         idx += (size_t)gridDim.x * blockDim.x) {
        float w = whh[idx];
        g_Wd[idx]  = to_tf32(w + g_fold[idx]);
        g_Wd0[idx] = to_tf32(w);
        if (idx < G4) {
            float b = bih[idx] + bhh[idx];
            g_bd[idx]  = b + g_foldb[idx];
            g_bd0[idx] = b;
        }
    }
}

// ================= launch =================
extern "C" void kernel_launch(void* const* d_in, const int* in_sizes, int n_in,
                              void* d_out, int out_size)
{
    const float* x     = (const float*)d_in[0];
    const float* Wih_e = (const float*)d_in[1];
    const float* Whh_e = (const float*)d_in[2];
    const float* bih_e = (const float*)d_in[3];
    const float* bhh_e = (const float*)d_in[4];
    const float* Wih_d = (const float*)d_in[5];
    const float* Whh_d = (const float*)d_in[6];
    const float* bih_d = (const float*)d_in[7];
    const float* bhh_d = (const float*)d_in[8];
    const float* Wfc   = (const float*)d_in[9];
    const float* bfc   = (const float*)d_in[10];
    const float* Wfcc  = (const float*)d_in[11];
    const float* bfcc  = (const float*)d_in[12];
    const float* Wout  = (const float*)d_in[13];
    const float* bout  = (const float*)d_in[14];
    float* out = (float*)d_out;

    float *p_xT, *p_We, *p_Wd, *p_Wd0, *p_fold, *p_Wfc, *p_Wfcc, *p_WoutT;
    float *p_be, *p_bd, *p_bd0;
    float *p_hA, *p_hB, *p_c, *p_cd, *p_hd;
    cudaGetSymbolAddress((void**)&p_xT, g_xT);
    cudaGetSymbolAddress((void**)&p_We, g_We);
    cudaGetSymbolAddress((void**)&p_Wd, g_Wd);
    cudaGetSymbolAddress((void**)&p_Wd0, g_Wd0);
    cudaGetSymbolAddress((void**)&p_fold, g_fold);
    cudaGetSymbolAddress((void**)&p_Wfc, g_Wfc);
    cudaGetSymbolAddress((void**)&p_Wfcc, g_Wfcc);
    cudaGetSymbolAddress((void**)&p_WoutT, g_WoutT);
    cudaGetSymbolAddress((void**)&p_be, g_be);
    cudaGetSymbolAddress((void**)&p_bd, g_bd);
    cudaGetSymbolAddress((void**)&p_bd0, g_bd0);
    cudaGetSymbolAddress((void**)&p_hA, g_hA);
    cudaGetSymbolAddress((void**)&p_hB, g_hB);
    cudaGetSymbolAddress((void**)&p_c, g_c);
    cudaGetSymbolAddress((void**)&p_cd, g_cd);
    cudaGetSymbolAddress((void**)&p_hd, g_hd_all);

    const int smem = 128 * 264 * (int)sizeof(float);  // 135168 B (>= 2 stages)
    cudaFuncSetAttribute(lstm_step<KT, true>,
                         cudaFuncAttributeMaxDynamicSharedMemorySize, smem);
    cudaFuncSetAttribute(lstm_step<HH, false>,
                         cudaFuncAttributeMaxDynamicSharedMemorySize, smem);

    // ---- prep: exactly 5 launches (ncu -s 5 profiles first lstm_step) ----
    k_prep_x<<<2048, 256>>>(x);                                          // 1
    k_prep_w<<<2048, 256>>>(Wih_e, Whh_e, bih_e, bhh_e, p_We, p_be);     // 2
    k_misc<<<2048, 256>>>(Wfc, Wfcc, Wout, Wih_d, bout);                 // 3
    linear_k<128, 128, false><<<dim3(32, 8), 256>>>(Wih_d, p_WoutT, nullptr,
                                                    p_fold, HH, nullptr, 0); // 4
    k_prep_wd<<<2048, 256>>>(Whh_d, bih_d, bhh_d);                       // 5

    // ---- encoder: 96 steps, h ping-pong ----
    float* hb[2] = {p_hA, p_hB};
    dim3 gstep(8, 16);
    for (int t = 0; t < SEQ; t++)
        lstm_step<KT, true><<<gstep, 256, smem>>>(
            p_xT + (size_t)t * BQ * IN, hb[t & 1], p_We, p_be, p_c, hb[(t + 1) & 1]);
    float* henc = hb[SEQ & 1];

    // ---- bridge: h_dec -> slice 0 of g_hd_all (tf32), c_dec -> g_cd ----
    linear_k<128, HH, false><<<dim3(8, 8), 256>>>(henc, p_Wfc, bfc,
                                                  nullptr, 0, p_hd, HH);
    linear_k<128, HH, false><<<dim3(8, 8), 256>>>(henc, p_Wfcc, bfcc,
                                                  p_cd, HH, nullptr, 0);

    // ---- decoder: step 0 plain W_hh (in0 = 0), steps 1..23 folded ----
    for (int t = 0; t < HOR; t++)
        lstm_step<HH, false><<<gstep, 256, smem>>>(
            nullptr, p_hd + (size_t)t * BQ * HH,
            (t == 0) ? p_Wd0 : p_Wd, (t == 0) ? p_bd0 : p_bd, p_cd,
            p_hd + (size_t)(t + 1) * BQ * HH);

    // ---- all 24 output projections in ONE batched GEMM ----
    linear_k<128, HH, true><<<dim3(HOR * BQ / 128, 1), 256>>>(
        p_hd + (size_t)BQ * HH, Wout, bout, out, 0, nullptr, 0);
}